// round 7
// baseline (speedup 1.0000x reference)
#include <cuda_runtime.h>
#include <math_constants.h>

#define NP    16384
#define GRIDD 32
#define NCELL (GRIDD * GRIDD * GRIDD)   // 32768
#define ORG   (-4.5f)
#define WID   (9.0f / GRIDD)            // 0.28125
#define INVW  (GRIDD / 9.0f)
#define FULLM 0xffffffffu
#define FXS   268435456.0f              // 2^28 fixed-point scale

// ---------------- device scratch (static, no allocs) ----------------
__device__ int    g_count[2][NCELL];
__device__ int2   g_meta[2][NCELL];     // (start, count)
__device__ int    g_cursor[2][NCELL];
__device__ float4 g_pts[2][NP];         // cell-sorted points
__device__ float  g_mind2[2 * NP];      // per-query min squared distance

__device__ __forceinline__ int clampi(int v, int lo, int hi) {
    return v < lo ? lo : (v > hi ? hi : v);
}
__device__ __forceinline__ void cell_of(float x, float y, float z,
                                        int& cx, int& cy, int& cz) {
    cx = clampi((int)floorf((x - ORG) * INVW), 0, GRIDD - 1);
    cy = clampi((int)floorf((y - ORG) * INVW), 0, GRIDD - 1);
    cz = clampi((int)floorf((z - ORG) * INVW), 0, GRIDD - 1);
}

// ---------------- kernel 1: zero cell counts ----------------
__global__ void zero_kernel() {
    int i = blockIdx.x * blockDim.x + threadIdx.x;
    if (i < 2 * NCELL) ((int*)g_count)[i] = 0;
}

// ---------------- kernel 2: count points per cell ----------------
__global__ __launch_bounds__(256)
void count_kernel(const float* __restrict__ pred, const float* __restrict__ gt) {
    int i = blockIdx.x * blockDim.x + threadIdx.x;   // [0, 2*NP)
    int cloud = i >> 14;
    int idx = i & (NP - 1);
    const float* r = (cloud ? gt : pred) + (size_t)idx * 6;
    int cx, cy, cz;
    cell_of(r[0], r[1], r[2], cx, cy, cz);
    atomicAdd(&g_count[cloud][(cz * GRIDD + cy) * GRIDD + cx], 1);
}

// ---------------- kernel 3: exclusive scan per cloud (1 block each) ----------------
__global__ __launch_bounds__(1024)
void scan_kernel() {
    const int a = blockIdx.x;        // cloud
    const int t = threadIdx.x;       // 1024 threads x 32 cells
    const int lane = t & 31, w = t >> 5;
    const int4* c4 = (const int4*)g_count[a];

    int s = 0;
#pragma unroll
    for (int i = 0; i < 8; i++) {
        int4 v = c4[t * 8 + i];
        s += v.x + v.y + v.z + v.w;
    }
    int si = s;
#pragma unroll
    for (int d = 1; d < 32; d <<= 1) {
        int v = __shfl_up_sync(FULLM, si, d);
        if (lane >= d) si += v;
    }
    __shared__ int ws[32];
    if (lane == 31) ws[w] = si;
    __syncthreads();
    if (w == 0) {
        int v = ws[lane];
        int vi = v;
#pragma unroll
        for (int d = 1; d < 32; d <<= 1) {
            int x = __shfl_up_sync(FULLM, vi, d);
            if (lane >= d) vi += x;
        }
        ws[lane] = vi - v;   // exclusive warp offsets
    }
    __syncthreads();
    int run = ws[w] + si - s;   // exclusive prefix for this thread's 32 cells

#pragma unroll
    for (int i = 0; i < 32; i++) {
        int c = g_count[a][t * 32 + i];
        g_meta[a][t * 32 + i] = make_int2(run, c);
        g_cursor[a][t * 32 + i] = run;
        run += c;
    }
}

// ---------------- kernel 4: scatter points into cell order ----------------
__global__ __launch_bounds__(256)
void scatter_kernel(const float* __restrict__ pred, const float* __restrict__ gt) {
    int i = blockIdx.x * blockDim.x + threadIdx.x;
    int cloud = i >> 14;
    int idx = i & (NP - 1);
    const float* r = (cloud ? gt : pred) + (size_t)idx * 6;
    float x = r[0], y = r[1], z = r[2];
    int cx, cy, cz;
    cell_of(x, y, z, cx, cy, cz);
    int pos = atomicAdd(&g_cursor[cloud][(cz * GRIDD + cy) * GRIDD + cx], 1);
    g_pts[cloud][pos] = make_float4(x, y, z, 0.0f);
}

// ---------------- kernel 5: exact NN, one WARP per query ----------------
// Phase 1: flattened 3x3x3 box, one meta round-trip, lane-strided stream.
// Fallback (~1% of queries): brute-force scan of ALL opposite-cloud points —
// independent loads, high MLP, bounded ~4-8K cycles (vs serial box walks).
__global__ __launch_bounds__(256)
void query_kernel() {
    const int lane = threadIdx.x & 31;
    const int gw   = (blockIdx.x * blockDim.x + threadIdx.x) >> 5;  // [0, 2*NP)
    const int dir  = gw >> 14;
    const int idx  = gw & (NP - 1);
    const int sdb  = dir ^ 1;

    float4 qp = g_pts[dir][idx];
    float qx = qp.x, qy = qp.y, qz = qp.z;
    int cx, cy, cz;
    cell_of(qx, qy, qz, cx, cy, cz);

    // face distances; grid-edge faces -> +INF (no cells beyond them)
    float f0 = (cx == GRIDD - 1) ? CUDART_INF_F : (cx + 1) * WID + ORG - qx;
    float f1 = (cx == 0)         ? CUDART_INF_F : qx - (cx * WID + ORG);
    float f2 = (cy == GRIDD - 1) ? CUDART_INF_F : (cy + 1) * WID + ORG - qy;
    float f3 = (cy == 0)         ? CUDART_INF_F : qy - (cy * WID + ORG);
    float f4 = (cz == GRIDD - 1) ? CUDART_INF_F : (cz + 1) * WID + ORG - qz;
    float f5 = (cz == 0)         ? CUDART_INF_F : qz - (cz * WID + ORG);
    float fmin6 = fminf(fminf(fminf(f0, f1), fminf(f2, f3)), fminf(f4, f5));

    const float4* __restrict__ pts  = g_pts[sdb];
    const int2*   __restrict__ meta = g_meta[sdb];

    float best = CUDART_INF_F;

    // -------- phase 1: flattened 3x3x3 box, single meta round-trip --------
    {
        int x0 = max(cx - 1, 0), x1 = min(cx + 1, GRIDD - 1);
        int s = 0, c = 0;
        if (lane < 9) {
            int zc = cz + lane / 3 - 1;
            int yc = cy + (lane % 3) - 1;
            if (zc >= 0 && zc < GRIDD && yc >= 0 && yc < GRIDD) {
                int base = (zc * GRIDD + yc) * GRIDD;
                int2 m0 = meta[base + x0];
                int2 m1 = meta[base + x1];
                s = m0.x;
                c = m1.x + m1.y - m0.x;
            }
        }
        int p = c;
#pragma unroll
        for (int d = 1; d < 16; d <<= 1) {
            int v = __shfl_up_sync(FULLM, p, d);
            if (lane >= d) p += v;
        }
        int E  = __shfl_sync(FULLM, p, 8);   // total candidates
        int pe = p - c;                       // exclusive prefix of this row
        int P[9], S[9];
#pragma unroll
        for (int r = 0; r < 9; r++) {
            P[r] = __shfl_sync(FULLM, pe, r);
            S[r] = __shfl_sync(FULLM, s,  r);
        }
        for (int i = lane; i < E; i += 32) {
            int addr = S[0] + i;
#pragma unroll
            for (int r = 1; r < 9; r++)
                if (i >= P[r]) addr = S[r] + (i - P[r]);
            float4 g = pts[addr];
            float dx = qx - g.x, dy = qy - g.y, dz = qz - g.z;
            best = fminf(best, fmaf(dx, dx, fmaf(dy, dy, dz * dz)));
        }
    }
#pragma unroll
    for (int sft = 16; sft > 0; sft >>= 1)
        best = fminf(best, __shfl_xor_sync(FULLM, best, sft));

    float bnd = WID + fmin6;   // unscanned points are >= bnd away
    if (!(best <= bnd * bnd)) {
        // -------- rare fallback: brute-force scan of the whole opposite cloud --------
        float b0 = CUDART_INF_F, b1 = CUDART_INF_F,
              b2 = CUDART_INF_F, b3 = CUDART_INF_F;
#pragma unroll 1
        for (int p = lane; p < NP; p += 128) {   // 4 independent streams
            float4 ga = pts[p];
            float4 gb = pts[p + 32];
            float4 gc = pts[p + 64];
            float4 gd = pts[p + 96];
            float dx, dy, dz;
            dx = qx - ga.x; dy = qy - ga.y; dz = qz - ga.z;
            b0 = fminf(b0, fmaf(dx, dx, fmaf(dy, dy, dz * dz)));
            dx = qx - gb.x; dy = qy - gb.y; dz = qz - gb.z;
            b1 = fminf(b1, fmaf(dx, dx, fmaf(dy, dy, dz * dz)));
            dx = qx - gc.x; dy = qy - gc.y; dz = qz - gc.z;
            b2 = fminf(b2, fmaf(dx, dx, fmaf(dy, dy, dz * dz)));
            dx = qx - gd.x; dy = qy - gd.y; dz = qz - gd.z;
            b3 = fminf(b3, fmaf(dx, dx, fmaf(dy, dy, dz * dz)));
        }
        best = fminf(fminf(b0, b1), fminf(b2, b3));
#pragma unroll
        for (int sft = 16; sft > 0; sft >>= 1)
            best = fminf(best, __shfl_xor_sync(FULLM, best, sft));
    }

    if (lane == 0) g_mind2[gw] = fmaxf(best, 0.0f);
}

// ---------------- kernel 6: fused final reduction ----------------
// Distance sum in int64 fixed point (2^-28): integer addition is
// permutation-invariant -> bit-deterministic despite race-ordered scatter.
__global__ __launch_bounds__(1024)
void reduce_kernel(const float* __restrict__ pred, const float* __restrict__ gt,
                   float* __restrict__ out) {
    const int t = threadIdx.x;

    long long sd = 0;
#pragma unroll
    for (int j = 0; j < 32; j++)
        sd += (long long)llrintf(sqrtf(g_mind2[t + j * 1024]) * FXS);

    float sc = 0.0f;
#pragma unroll
    for (int j = 0; j < 48; j++) {
        int ce = t + j * 1024;          // [0, 49152)
        int i = ce / 3, c = ce - 3 * i;
        sc += fabsf(pred[(size_t)i * 6 + 3 + c] - gt[(size_t)i * 6 + 3 + c]);
    }

    __shared__ long long s1[1024];
    __shared__ float s2[1024];
    s1[t] = sd;
    s2[t] = sc;
    __syncthreads();
#pragma unroll
    for (int s = 512; s > 0; s >>= 1) {
        if (t < s) { s1[t] += s1[t + s]; s2[t] += s2[t + s]; }
        __syncthreads();
    }
    if (t == 0) {
        double dist_sum = (double)s1[0] * (1.0 / (double)FXS);
        out[0] = (float)(dist_sum / (double)NP) + 0.1f * s2[0] * (1.0f / (float)(NP * 3));
    }
}

extern "C" void kernel_launch(void* const* d_in, const int* in_sizes, int n_in,
                              void* d_out, int out_size) {
    const float* pred = (const float*)d_in[0];
    const float* gt   = (const float*)d_in[1];
    float* out        = (float*)d_out;
    (void)in_sizes; (void)n_in; (void)out_size;

    zero_kernel<<<(2 * NCELL + 1023) / 1024, 1024>>>();
    count_kernel<<<(2 * NP) / 256, 256>>>(pred, gt);
    scan_kernel<<<2, 1024>>>();
    scatter_kernel<<<(2 * NP) / 256, 256>>>(pred, gt);
    query_kernel<<<(2 * NP * 32) / 256, 256>>>();
    reduce_kernel<<<1, 1024>>>(pred, gt, out);
}

// round 8
// speedup vs baseline: 1.0712x; 1.0712x over previous
#include <cuda_runtime.h>
#include <math_constants.h>

#define NP    16384
#define GRIDD 32
#define NCELL (GRIDD * GRIDD * GRIDD)   // 32768
#define ORG   (-4.5f)
#define WID   (9.0f / GRIDD)            // 0.28125
#define INVW  (GRIDD / 9.0f)
#define FULLM 0xffffffffu
#define FXS   268435456.0f              // 2^28 fixed-point scale
#define FBLKS 256

// ---------------- device scratch (static, no allocs) ----------------
__device__ int    g_count[2][NCELL];
__device__ int2   g_meta[2][NCELL];     // (start, count)
__device__ int    g_cursor[2][NCELL];
__device__ float4 g_pts[2][NP];         // cell-sorted points
__device__ float  g_mind2[2 * NP];      // per-query min squared distance
__device__ int    g_nfail;
__device__ int    g_fail[2 * NP];

__device__ __forceinline__ int clampi(int v, int lo, int hi) {
    return v < lo ? lo : (v > hi ? hi : v);
}
__device__ __forceinline__ void cell_of(float x, float y, float z,
                                        int& cx, int& cy, int& cz) {
    cx = clampi((int)floorf((x - ORG) * INVW), 0, GRIDD - 1);
    cy = clampi((int)floorf((y - ORG) * INVW), 0, GRIDD - 1);
    cz = clampi((int)floorf((z - ORG) * INVW), 0, GRIDD - 1);
}

// ---------------- kernel 1: zero counts + fail counter ----------------
__global__ void zero_kernel() {
    int i = blockIdx.x * blockDim.x + threadIdx.x;
    if (i < 2 * NCELL) ((int*)g_count)[i] = 0;
    if (i == 0) g_nfail = 0;
}

// ---------------- kernel 2: count points per cell ----------------
__global__ __launch_bounds__(256)
void count_kernel(const float* __restrict__ pred, const float* __restrict__ gt) {
    int i = blockIdx.x * blockDim.x + threadIdx.x;   // [0, 2*NP)
    int cloud = i >> 14;
    int idx = i & (NP - 1);
    const float* r = (cloud ? gt : pred) + (size_t)idx * 6;
    int cx, cy, cz;
    cell_of(r[0], r[1], r[2], cx, cy, cz);
    atomicAdd(&g_count[cloud][(cz * GRIDD + cy) * GRIDD + cx], 1);
}

// ---------------- kernel 3: exclusive scan per cloud (1 block each) ----------------
__global__ __launch_bounds__(1024)
void scan_kernel() {
    const int a = blockIdx.x;        // cloud
    const int t = threadIdx.x;       // 1024 threads x 32 cells
    const int lane = t & 31, w = t >> 5;
    const int4* c4 = (const int4*)g_count[a];

    int s = 0;
#pragma unroll
    for (int i = 0; i < 8; i++) {
        int4 v = c4[t * 8 + i];
        s += v.x + v.y + v.z + v.w;
    }
    int si = s;
#pragma unroll
    for (int d = 1; d < 32; d <<= 1) {
        int v = __shfl_up_sync(FULLM, si, d);
        if (lane >= d) si += v;
    }
    __shared__ int ws[32];
    if (lane == 31) ws[w] = si;
    __syncthreads();
    if (w == 0) {
        int v = ws[lane];
        int vi = v;
#pragma unroll
        for (int d = 1; d < 32; d <<= 1) {
            int x = __shfl_up_sync(FULLM, vi, d);
            if (lane >= d) vi += x;
        }
        ws[lane] = vi - v;   // exclusive warp offsets
    }
    __syncthreads();
    int run = ws[w] + si - s;   // exclusive prefix for this thread's 32 cells

#pragma unroll
    for (int i = 0; i < 32; i++) {
        int c = g_count[a][t * 32 + i];
        g_meta[a][t * 32 + i] = make_int2(run, c);
        g_cursor[a][t * 32 + i] = run;
        run += c;
    }
}

// ---------------- kernel 4: scatter points into cell order ----------------
__global__ __launch_bounds__(256)
void scatter_kernel(const float* __restrict__ pred, const float* __restrict__ gt) {
    int i = blockIdx.x * blockDim.x + threadIdx.x;
    int cloud = i >> 14;
    int idx = i & (NP - 1);
    const float* r = (cloud ? gt : pred) + (size_t)idx * 6;
    float x = r[0], y = r[1], z = r[2];
    int cx, cy, cz;
    cell_of(x, y, z, cx, cy, cz);
    int pos = atomicAdd(&g_cursor[cloud][(cz * GRIDD + cy) * GRIDD + cx], 1);
    g_pts[cloud][pos] = make_float4(x, y, z, 0.0f);
}

// ---------------- kernel 5: phase-1 NN, one WARP per query ----------------
// Flattened 3x3x3 box, one meta round-trip, lane-strided candidate stream.
// On bound failure, append query id to the failure list (handled by kernel 5b).
__global__ __launch_bounds__(256)
void query_kernel() {
    const int lane = threadIdx.x & 31;
    const int gw   = (blockIdx.x * blockDim.x + threadIdx.x) >> 5;  // [0, 2*NP)
    const int dir  = gw >> 14;
    const int idx  = gw & (NP - 1);
    const int sdb  = dir ^ 1;

    float4 qp = g_pts[dir][idx];
    float qx = qp.x, qy = qp.y, qz = qp.z;
    int cx, cy, cz;
    cell_of(qx, qy, qz, cx, cy, cz);

    // face distances; grid-edge faces -> +INF (no cells beyond them)
    float f0 = (cx == GRIDD - 1) ? CUDART_INF_F : (cx + 1) * WID + ORG - qx;
    float f1 = (cx == 0)         ? CUDART_INF_F : qx - (cx * WID + ORG);
    float f2 = (cy == GRIDD - 1) ? CUDART_INF_F : (cy + 1) * WID + ORG - qy;
    float f3 = (cy == 0)         ? CUDART_INF_F : qy - (cy * WID + ORG);
    float f4 = (cz == GRIDD - 1) ? CUDART_INF_F : (cz + 1) * WID + ORG - qz;
    float f5 = (cz == 0)         ? CUDART_INF_F : qz - (cz * WID + ORG);
    float fmin6 = fminf(fminf(fminf(f0, f1), fminf(f2, f3)), fminf(f4, f5));

    const float4* __restrict__ pts  = g_pts[sdb];
    const int2*   __restrict__ meta = g_meta[sdb];

    float best = CUDART_INF_F;

    {
        int x0 = max(cx - 1, 0), x1 = min(cx + 1, GRIDD - 1);
        int s = 0, c = 0;
        if (lane < 9) {
            int zc = cz + lane / 3 - 1;
            int yc = cy + (lane % 3) - 1;
            if (zc >= 0 && zc < GRIDD && yc >= 0 && yc < GRIDD) {
                int base = (zc * GRIDD + yc) * GRIDD;
                int2 m0 = meta[base + x0];
                int2 m1 = meta[base + x1];
                s = m0.x;
                c = m1.x + m1.y - m0.x;
            }
        }
        int p = c;
#pragma unroll
        for (int d = 1; d < 16; d <<= 1) {
            int v = __shfl_up_sync(FULLM, p, d);
            if (lane >= d) p += v;
        }
        int E  = __shfl_sync(FULLM, p, 8);   // total candidates
        int pe = p - c;                       // exclusive prefix of this row
        int P[9], S[9];
#pragma unroll
        for (int r = 0; r < 9; r++) {
            P[r] = __shfl_sync(FULLM, pe, r);
            S[r] = __shfl_sync(FULLM, s,  r);
        }
        for (int i = lane; i < E; i += 32) {
            int addr = S[0] + i;
#pragma unroll
            for (int r = 1; r < 9; r++)
                if (i >= P[r]) addr = S[r] + (i - P[r]);
            float4 g = pts[addr];
            float dx = qx - g.x, dy = qy - g.y, dz = qz - g.z;
            best = fminf(best, fmaf(dx, dx, fmaf(dy, dy, dz * dz)));
        }
    }
#pragma unroll
    for (int sft = 16; sft > 0; sft >>= 1)
        best = fminf(best, __shfl_xor_sync(FULLM, best, sft));

    float bnd = WID + fmin6;   // unscanned points are >= bnd away
    if (lane == 0) {
        if (best <= bnd * bnd) {
            g_mind2[gw] = fmaxf(best, 0.0f);
        } else {
            int slot = atomicAdd(&g_nfail, 1);
            g_fail[slot] = gw;               // exact value written by fallback
        }
    }
}

// ---------------- kernel 5b: fallback, one BLOCK per failed query ----------------
// Full scan of the opposite cloud: 64 independent loads per thread across 256
// threads -> latency fully amortized. Fixed-order tree reduce -> deterministic.
__global__ __launch_bounds__(256)
void fallback_kernel() {
    __shared__ float sm[256];
    const int t = threadIdx.x;
    const int nf = g_nfail;

    for (int f = blockIdx.x; f < nf; f += FBLKS) {
        int gw  = g_fail[f];
        int dir = gw >> 14;
        int idx = gw & (NP - 1);
        const float4* __restrict__ pts = g_pts[dir ^ 1];

        float4 qp = g_pts[dir][idx];
        float qx = qp.x, qy = qp.y, qz = qp.z;

        float b0 = CUDART_INF_F, b1 = CUDART_INF_F;
#pragma unroll 8
        for (int p = t; p < NP; p += 512) {     // 2 streams x 32 iters, unroll 8
            float4 ga = pts[p];
            float4 gb = pts[p + 256];
            float dx, dy, dz;
            dx = qx - ga.x; dy = qy - ga.y; dz = qz - ga.z;
            b0 = fminf(b0, fmaf(dx, dx, fmaf(dy, dy, dz * dz)));
            dx = qx - gb.x; dy = qy - gb.y; dz = qz - gb.z;
            b1 = fminf(b1, fmaf(dx, dx, fmaf(dy, dy, dz * dz)));
        }
        sm[t] = fminf(b0, b1);
        __syncthreads();
#pragma unroll
        for (int s = 128; s > 0; s >>= 1) {
            if (t < s) sm[t] = fminf(sm[t], sm[t + s]);
            __syncthreads();
        }
        if (t == 0) g_mind2[gw] = fmaxf(sm[0], 0.0f);
        __syncthreads();
    }
}

// ---------------- kernel 6: fused final reduction ----------------
// Distance sum in int64 fixed point (2^-28): integer addition is
// permutation-invariant -> bit-deterministic despite race-ordered scatter.
__global__ __launch_bounds__(1024)
void reduce_kernel(const float* __restrict__ pred, const float* __restrict__ gt,
                   float* __restrict__ out) {
    const int t = threadIdx.x;

    long long sd = 0;
#pragma unroll
    for (int j = 0; j < 32; j++)
        sd += (long long)llrintf(sqrtf(g_mind2[t + j * 1024]) * FXS);

    float sc = 0.0f;
#pragma unroll
    for (int j = 0; j < 48; j++) {
        int ce = t + j * 1024;          // [0, 49152)
        int i = ce / 3, c = ce - 3 * i;
        sc += fabsf(pred[(size_t)i * 6 + 3 + c] - gt[(size_t)i * 6 + 3 + c]);
    }

    __shared__ long long s1[1024];
    __shared__ float s2[1024];
    s1[t] = sd;
    s2[t] = sc;
    __syncthreads();
#pragma unroll
    for (int s = 512; s > 0; s >>= 1) {
        if (t < s) { s1[t] += s1[t + s]; s2[t] += s2[t + s]; }
        __syncthreads();
    }
    if (t == 0) {
        double dist_sum = (double)s1[0] * (1.0 / (double)FXS);
        out[0] = (float)(dist_sum / (double)NP) + 0.1f * s2[0] * (1.0f / (float)(NP * 3));
    }
}

extern "C" void kernel_launch(void* const* d_in, const int* in_sizes, int n_in,
                              void* d_out, int out_size) {
    const float* pred = (const float*)d_in[0];
    const float* gt   = (const float*)d_in[1];
    float* out        = (float*)d_out;
    (void)in_sizes; (void)n_in; (void)out_size;

    zero_kernel<<<(2 * NCELL + 1023) / 1024, 1024>>>();
    count_kernel<<<(2 * NP) / 256, 256>>>(pred, gt);
    scan_kernel<<<2, 1024>>>();
    scatter_kernel<<<(2 * NP) / 256, 256>>>(pred, gt);
    query_kernel<<<(2 * NP * 32) / 256, 256>>>();
    fallback_kernel<<<FBLKS, 256>>>();
    reduce_kernel<<<1, 1024>>>(pred, gt, out);
}

// round 9
// speedup vs baseline: 1.3650x; 1.2742x over previous
#include <cuda_runtime.h>
#include <math_constants.h>

#define NP    16384
#define GRIDD 32
#define NCELL (GRIDD * GRIDD * GRIDD)   // 32768
#define ORG   (-4.5f)
#define WID   (9.0f / GRIDD)            // 0.28125
#define INVW  (GRIDD / 9.0f)
#define FULLM 0xffffffffu
#define FXS   268435456.0f              // 2^28 fixed-point scale
#define CAP   64
#define OVCAP 1024

// ---------------- device scratch (static, zero-init at load; each run
// re-zeroes the counters for the next run in reduce_kernel) ----------------
__device__ int    g_count[2][NCELL];        // per-cell point counts
__device__ float4 g_bkt[2][NCELL * CAP];    // bucket storage
__device__ float4 g_dense[2][NP];           // dense copy (index-ordered: deterministic)
__device__ int    g_ovf_n[2];
__device__ float4 g_ovf[2][OVCAP];
__device__ float  g_mind2[2 * NP];

__device__ __forceinline__ int clampi(int v, int lo, int hi) {
    return v < lo ? lo : (v > hi ? hi : v);
}
__device__ __forceinline__ void cell_of(float x, float y, float z,
                                        int& cx, int& cy, int& cz) {
    cx = clampi((int)floorf((x - ORG) * INVW), 0, GRIDD - 1);
    cy = clampi((int)floorf((y - ORG) * INVW), 0, GRIDD - 1);
    cz = clampi((int)floorf((z - ORG) * INVW), 0, GRIDD - 1);
}

// ---------------- node 1: bin points into buckets + dense copy ----------------
__global__ __launch_bounds__(256)
void bin_kernel(const float* __restrict__ pred, const float* __restrict__ gt) {
    int i = blockIdx.x * blockDim.x + threadIdx.x;   // [0, 2*NP)
    int cloud = i >> 14;
    int idx = i & (NP - 1);
    const float* r = (cloud ? gt : pred) + (size_t)idx * 6;
    float x = r[0], y = r[1], z = r[2];
    float4 pt = make_float4(x, y, z, 0.0f);
    g_dense[cloud][idx] = pt;

    int cx, cy, cz;
    cell_of(x, y, z, cx, cy, cz);
    int cell = (cz * GRIDD + cy) * GRIDD + cx;
    int slot = atomicAdd(&g_count[cloud][cell], 1);
    if (slot < CAP) {
        g_bkt[cloud][cell * CAP + slot] = pt;
    } else {
        int o = atomicAdd(&g_ovf_n[cloud], 1);
        if (o < OVCAP) g_ovf[cloud][o] = pt;
    }
}

// warp-cooperative scan of the (2k+1)^3 box around (cx,cy,cz)
__device__ __forceinline__ float scan_box(
    const int* __restrict__ cnts, const float4* __restrict__ bkt,
    int cx, int cy, int cz, int k, int lane,
    float qx, float qy, float qz, float best)
{
    const int W = 2 * k + 1;
    const int ncell = W * W * W;
    for (int cb = 0; cb < ncell; cb += 32) {
        int cc = cb + lane;
        int cnt = 0, base = 0;
        if (cc < ncell) {
            int dz = cc / (W * W), rem = cc - dz * W * W;
            int dy = rem / W, dx = rem - dy * W;
            int zc = cz + dz - k, yc = cy + dy - k, xc = cx + dx - k;
            if ((unsigned)zc < GRIDD && (unsigned)yc < GRIDD && (unsigned)xc < GRIDD) {
                int cell = (zc * GRIDD + yc) * GRIDD + xc;
                cnt = min(cnts[cell], CAP);
                base = cell * CAP;
            }
        }
        unsigned nz = __ballot_sync(FULLM, cnt > 0);
        while (nz) {
            int r = __ffs(nz) - 1;
            nz &= nz - 1;
            int bs = __shfl_sync(FULLM, base, r);
            int ct = __shfl_sync(FULLM, cnt, r);
            for (int p = lane; p < ct; p += 32) {
                float4 g = bkt[bs + p];
                float dx = qx - g.x, dy = qy - g.y, dz = qz - g.z;
                best = fminf(best, fmaf(dx, dx, fmaf(dy, dy, dz * dz)));
            }
        }
    }
    return best;
}

__device__ __forceinline__ float warp_min(float v) {
#pragma unroll
    for (int s = 16; s > 0; s >>= 1)
        v = fminf(v, __shfl_xor_sync(FULLM, v, s));
    return v;
}

// ---------------- node 2: exact NN, one WARP per query ----------------
__global__ __launch_bounds__(256)
void query_kernel(const float* __restrict__ pred, const float* __restrict__ gt) {
    const int lane = threadIdx.x & 31;
    const int gw   = (blockIdx.x * blockDim.x + threadIdx.x) >> 5;  // [0, 2*NP)
    const int dir  = gw >> 14;
    const int idx  = gw & (NP - 1);
    const int sdb  = dir ^ 1;

    const float* q = (dir ? gt : pred) + (size_t)idx * 6;
    float qx = q[0], qy = q[1], qz = q[2];   // broadcast loads
    int cx, cy, cz;
    cell_of(qx, qy, qz, cx, cy, cz);

    // face distances; grid-edge faces -> +INF (no cells beyond them).
    // NOTE: clamped outliers sit outside their cell -> fmin6 can be negative;
    // all bound checks below require bnd > 0.
    float f0 = (cx == GRIDD - 1) ? CUDART_INF_F : (cx + 1) * WID + ORG - qx;
    float f1 = (cx == 0)         ? CUDART_INF_F : qx - (cx * WID + ORG);
    float f2 = (cy == GRIDD - 1) ? CUDART_INF_F : (cy + 1) * WID + ORG - qy;
    float f3 = (cy == 0)         ? CUDART_INF_F : qy - (cy * WID + ORG);
    float f4 = (cz == GRIDD - 1) ? CUDART_INF_F : (cz + 1) * WID + ORG - qz;
    float f5 = (cz == 0)         ? CUDART_INF_F : qz - (cz * WID + ORG);
    float fmin6 = fminf(fminf(fminf(f0, f1), fminf(f2, f3)), fminf(f4, f5));

    const int*    __restrict__ cnts = g_count[sdb];
    const float4* __restrict__ bkt  = g_bkt[sdb];

    float best = CUDART_INF_F;

    // overflow points of the opposite cloud (normally 0) — scanned once,
    // valid for every later bound check.
    int novf = min(g_ovf_n[sdb], OVCAP);
    for (int p = lane; p < novf; p += 32) {
        float4 g = g_ovf[sdb][p];
        float dx = qx - g.x, dy = qy - g.y, dz = qz - g.z;
        best = fminf(best, fmaf(dx, dx, fmaf(dy, dy, dz * dz)));
    }

    // -------- phase A: 3x3x3 box --------
    best = scan_box(cnts, bkt, cx, cy, cz, 1, lane, qx, qy, qz, best);
    best = warp_min(best);
    float bnd = WID + fmin6;
    if (!(bnd > 0.0f && best <= bnd * bnd)) {
        // -------- phase B: 5x5x5 box (rescans inner; rare) --------
        best = scan_box(cnts, bkt, cx, cy, cz, 2, lane, qx, qy, qz, best);
        best = warp_min(best);
        bnd = 2.0f * WID + fmin6;
        if (!(bnd > 0.0f && best <= bnd * bnd)) {
            // -------- phase C: brute over dense copy (deep MLP; ~100 warps) --------
            const float4* __restrict__ dns = g_dense[sdb];
#pragma unroll 16
            for (int p = lane; p < NP; p += 32) {
                float4 g = dns[p];
                float dx = qx - g.x, dy = qy - g.y, dz = qz - g.z;
                best = fminf(best, fmaf(dx, dx, fmaf(dy, dy, dz * dz)));
            }
            best = warp_min(best);
        }
    }

    if (lane == 0) g_mind2[gw] = fmaxf(best, 0.0f);
}

// ---------------- node 3: final reduction + counter reset for next run ----------------
// Distance sum in int64 fixed point (2^-28): integer addition is
// permutation-invariant -> bit-deterministic despite race-ordered binning.
__global__ __launch_bounds__(1024)
void reduce_kernel(const float* __restrict__ pred, const float* __restrict__ gt,
                   float* __restrict__ out) {
    const int t = threadIdx.x;

    long long sd = 0;
#pragma unroll
    for (int j = 0; j < 32; j++)
        sd += (long long)llrintf(sqrtf(g_mind2[t + j * 1024]) * FXS);

    float sc = 0.0f;
#pragma unroll
    for (int j = 0; j < 48; j++) {
        int ce = t + j * 1024;          // [0, 49152)
        int i = ce / 3, c = ce - 3 * i;
        sc += fabsf(pred[(size_t)i * 6 + 3 + c] - gt[(size_t)i * 6 + 3 + c]);
    }

    // reset counters for the next execution (first run relies on zero-init)
    int* cc = (int*)g_count;
#pragma unroll
    for (int j = 0; j < 64; j++)
        cc[t + j * 1024] = 0;
    if (t == 0) { g_ovf_n[0] = 0; g_ovf_n[1] = 0; }

    __shared__ long long s1[1024];
    __shared__ float s2[1024];
    s1[t] = sd;
    s2[t] = sc;
    __syncthreads();
#pragma unroll
    for (int s = 512; s > 0; s >>= 1) {
        if (t < s) { s1[t] += s1[t + s]; s2[t] += s2[t + s]; }
        __syncthreads();
    }
    if (t == 0) {
        double dist_sum = (double)s1[0] * (1.0 / (double)FXS);
        out[0] = (float)(dist_sum / (double)NP) + 0.1f * s2[0] * (1.0f / (float)(NP * 3));
    }
}

extern "C" void kernel_launch(void* const* d_in, const int* in_sizes, int n_in,
                              void* d_out, int out_size) {
    const float* pred = (const float*)d_in[0];
    const float* gt   = (const float*)d_in[1];
    float* out        = (float*)d_out;
    (void)in_sizes; (void)n_in; (void)out_size;

    bin_kernel<<<(2 * NP) / 256, 256>>>(pred, gt);
    query_kernel<<<(2 * NP * 32) / 256, 256>>>(pred, gt);
    reduce_kernel<<<1, 1024>>>(pred, gt, out);
}

// round 10
// speedup vs baseline: 1.3748x; 1.0072x over previous
#include <cuda_runtime.h>
#include <math_constants.h>

#define NP    16384
#define GRIDD 32
#define NCELL (GRIDD * GRIDD * GRIDD)   // 32768
#define ORG   (-4.5f)
#define WID   (9.0f / GRIDD)            // 0.28125
#define INVW  (GRIDD / 9.0f)
#define FULLM 0xffffffffu
#define FXS   268435456.0f              // 2^28 fixed-point scale
#define CAP   64
#define OVCAP 1024

// ---------------- device scratch (static, zero-init at load; each run
// re-zeroes the counters for the next run in reduce_kernel) ----------------
__device__ int    g_count[2][NCELL];        // per-cell point counts
__device__ float4 g_bkt[2][NCELL * CAP];    // bucket storage
__device__ float4 g_dense[2][NP];           // dense copy (index-ordered)
__device__ int    g_ovf_n[2];
__device__ float4 g_ovf[2][OVCAP];
__device__ float  g_mind2[2 * NP];

__device__ __forceinline__ int clampi(int v, int lo, int hi) {
    return v < lo ? lo : (v > hi ? hi : v);
}
__device__ __forceinline__ void cell_of(float x, float y, float z,
                                        int& cx, int& cy, int& cz) {
    cx = clampi((int)floorf((x - ORG) * INVW), 0, GRIDD - 1);
    cy = clampi((int)floorf((y - ORG) * INVW), 0, GRIDD - 1);
    cz = clampi((int)floorf((z - ORG) * INVW), 0, GRIDD - 1);
}
__device__ __forceinline__ float warp_min(float v) {
#pragma unroll
    for (int s = 16; s > 0; s >>= 1)
        v = fminf(v, __shfl_xor_sync(FULLM, v, s));
    return v;
}

// ---------------- node 1: bin points into buckets + dense copy ----------------
__global__ __launch_bounds__(256)
void bin_kernel(const float* __restrict__ pred, const float* __restrict__ gt) {
    int i = blockIdx.x * blockDim.x + threadIdx.x;   // [0, 2*NP)
    int cloud = i >> 14;
    int idx = i & (NP - 1);
    const float* r = (cloud ? gt : pred) + (size_t)idx * 6;
    float x = r[0], y = r[1], z = r[2];
    float4 pt = make_float4(x, y, z, 0.0f);
    g_dense[cloud][idx] = pt;

    int cx, cy, cz;
    cell_of(x, y, z, cx, cy, cz);
    int cell = (cz * GRIDD + cy) * GRIDD + cx;
    int slot = atomicAdd(&g_count[cloud][cell], 1);
    if (slot < CAP) {
        g_bkt[cloud][cell * CAP + slot] = pt;
    } else {
        int o = atomicAdd(&g_ovf_n[cloud], 1);
        if (o < OVCAP) g_ovf[cloud][o] = pt;
    }
}

// ---------------- node 2: exact NN, one WARP per query ----------------
// Phase A: flattened 3x3x3 — ONE lane-parallel meta round trip, then the
// candidate set streams as independent loads (flat index -> (cell,offset)
// via a predicated select chain over the prefix-scan in registers).
// Phase B: same, 5x5x5 in 4 chunks (rare). Phase C: 32-MLP brute (rarer).
__global__ __launch_bounds__(256)
void query_kernel(const float* __restrict__ pred, const float* __restrict__ gt) {
    const int lane = threadIdx.x & 31;
    const int gw   = (blockIdx.x * blockDim.x + threadIdx.x) >> 5;  // [0, 2*NP)
    const int dir  = gw >> 14;
    const int idx  = gw & (NP - 1);
    const int sdb  = dir ^ 1;

    const float* q = (dir ? gt : pred) + (size_t)idx * 6;
    float qx = q[0], qy = q[1], qz = q[2];   // broadcast loads
    int cx, cy, cz;
    cell_of(qx, qy, qz, cx, cy, cz);

    // face distances; grid-edge faces -> +INF. Clamped outliers can sit
    // outside their cell -> fmin6 may be negative; bound checks need bnd > 0.
    float f0 = (cx == GRIDD - 1) ? CUDART_INF_F : (cx + 1) * WID + ORG - qx;
    float f1 = (cx == 0)         ? CUDART_INF_F : qx - (cx * WID + ORG);
    float f2 = (cy == GRIDD - 1) ? CUDART_INF_F : (cy + 1) * WID + ORG - qy;
    float f3 = (cy == 0)         ? CUDART_INF_F : qy - (cy * WID + ORG);
    float f4 = (cz == GRIDD - 1) ? CUDART_INF_F : (cz + 1) * WID + ORG - qz;
    float f5 = (cz == 0)         ? CUDART_INF_F : qz - (cz * WID + ORG);
    float fmin6 = fminf(fminf(fminf(f0, f1), fminf(f2, f3)), fminf(f4, f5));

    const int*    __restrict__ cnts = g_count[sdb];
    const float4* __restrict__ bkt  = g_bkt[sdb];

    float best = CUDART_INF_F;

    // overflow points of the opposite cloud (normally 0)
    int novf = min(g_ovf_n[sdb], OVCAP);
    for (int p = lane; p < novf; p += 32) {
        float4 g = g_ovf[sdb][p];
        float dx = qx - g.x, dy = qy - g.y, dz = qz - g.z;
        best = fminf(best, fmaf(dx, dx, fmaf(dy, dy, dz * dz)));
    }

    // -------- phase A: flattened 3x3x3 --------
    {
        int s = 0, c = 0;
        if (lane < 27) {
            int dz = lane / 9, rem = lane - dz * 9;
            int dy = rem / 3, dx = rem - dy * 3;
            int zc = cz + dz - 1, yc = cy + dy - 1, xc = cx + dx - 1;
            if ((unsigned)zc < GRIDD && (unsigned)yc < GRIDD && (unsigned)xc < GRIDD) {
                int cell = (zc * GRIDD + yc) * GRIDD + xc;
                c = min(cnts[cell], CAP);
                s = cell * CAP;
            }
        }
        int p = c;
#pragma unroll
        for (int d = 1; d < 32; d <<= 1) {
            int v = __shfl_up_sync(FULLM, p, d);
            if (lane >= d) p += v;
        }
        int E  = __shfl_sync(FULLM, p, 26);
        int pe = p - c;
        int S[27], P[27];
#pragma unroll
        for (int r = 0; r < 27; r++) {
            S[r] = __shfl_sync(FULLM, s,  r);
            P[r] = __shfl_sync(FULLM, pe, r);
        }
        for (int i = lane; i < E; i += 32) {
            int addr = S[0] + i;
#pragma unroll
            for (int r = 1; r < 27; r++)
                if (i >= P[r]) addr = S[r] + (i - P[r]);
            float4 g = bkt[addr];
            float dx = qx - g.x, dy = qy - g.y, dz = qz - g.z;
            best = fminf(best, fmaf(dx, dx, fmaf(dy, dy, dz * dz)));
        }
    }
    best = warp_min(best);

    float bnd = WID + fmin6;
    if (!(bnd > 0.0f && best <= bnd * bnd)) {
        // -------- phase B: flattened 5x5x5 in 4 chunks (rescans inner; rare) ----
        for (int cb = 0; cb < 125; cb += 32) {
            int cc = cb + lane;
            int s = 0, c = 0;
            if (cc < 125) {
                int dz = cc / 25, rem = cc - dz * 25;
                int dy = rem / 5, dx = rem - dy * 5;
                int zc = cz + dz - 2, yc = cy + dy - 2, xc = cx + dx - 2;
                if ((unsigned)zc < GRIDD && (unsigned)yc < GRIDD && (unsigned)xc < GRIDD) {
                    int cell = (zc * GRIDD + yc) * GRIDD + xc;
                    c = min(cnts[cell], CAP);
                    s = cell * CAP;
                }
            }
            int p = c;
#pragma unroll
            for (int d = 1; d < 32; d <<= 1) {
                int v = __shfl_up_sync(FULLM, p, d);
                if (lane >= d) p += v;
            }
            int E  = __shfl_sync(FULLM, p, 31);
            int pe = p - c;
            int S[32], P[32];
#pragma unroll
            for (int r = 0; r < 32; r++) {
                S[r] = __shfl_sync(FULLM, s,  r);
                P[r] = __shfl_sync(FULLM, pe, r);
            }
            for (int i = lane; i < E; i += 32) {
                int addr = S[0] + i;
#pragma unroll
                for (int r = 1; r < 32; r++)
                    if (i >= P[r]) addr = S[r] + (i - P[r]);
                float4 g = bkt[addr];
                float dx = qx - g.x, dy = qy - g.y, dz = qz - g.z;
                best = fminf(best, fmaf(dx, dx, fmaf(dy, dy, dz * dz)));
            }
        }
        best = warp_min(best);
        bnd = 2.0f * WID + fmin6;
        if (!(bnd > 0.0f && best <= bnd * bnd)) {
            // -------- phase C: brute over dense copy, 4 streams x unroll 8 ----
            const float4* __restrict__ dns = g_dense[sdb];
            float b0 = CUDART_INF_F, b1 = CUDART_INF_F,
                  b2 = CUDART_INF_F, b3 = CUDART_INF_F;
#pragma unroll 8
            for (int p = lane; p < NP; p += 128) {
                float4 ga = dns[p];
                float4 gb = dns[p + 32];
                float4 gc = dns[p + 64];
                float4 gd = dns[p + 96];
                float dx, dy, dz;
                dx = qx - ga.x; dy = qy - ga.y; dz = qz - ga.z;
                b0 = fminf(b0, fmaf(dx, dx, fmaf(dy, dy, dz * dz)));
                dx = qx - gb.x; dy = qy - gb.y; dz = qz - gb.z;
                b1 = fminf(b1, fmaf(dx, dx, fmaf(dy, dy, dz * dz)));
                dx = qx - gc.x; dy = qy - gc.y; dz = qz - gc.z;
                b2 = fminf(b2, fmaf(dx, dx, fmaf(dy, dy, dz * dz)));
                dx = qx - gd.x; dy = qy - gd.y; dz = qz - gd.z;
                b3 = fminf(b3, fmaf(dx, dx, fmaf(dy, dy, dz * dz)));
            }
            best = warp_min(fminf(fminf(b0, b1), fminf(b2, b3)));
        }
    }

    if (lane == 0) g_mind2[gw] = fmaxf(best, 0.0f);
}

// ---------------- node 3: final reduction + counter reset for next run ----------------
__global__ __launch_bounds__(1024)
void reduce_kernel(const float* __restrict__ pred, const float* __restrict__ gt,
                   float* __restrict__ out) {
    const int t = threadIdx.x;

    long long sd = 0;
#pragma unroll
    for (int j = 0; j < 32; j++)
        sd += (long long)llrintf(sqrtf(g_mind2[t + j * 1024]) * FXS);

    float sc = 0.0f;
#pragma unroll
    for (int j = 0; j < 48; j++) {
        int ce = t + j * 1024;          // [0, 49152)
        int i = ce / 3, c = ce - 3 * i;
        sc += fabsf(pred[(size_t)i * 6 + 3 + c] - gt[(size_t)i * 6 + 3 + c]);
    }

    // reset counters for the next execution (first run relies on zero-init)
    int* cc = (int*)g_count;
#pragma unroll
    for (int j = 0; j < 64; j++)
        cc[t + j * 1024] = 0;
    if (t == 0) { g_ovf_n[0] = 0; g_ovf_n[1] = 0; }

    __shared__ long long s1[1024];
    __shared__ float s2[1024];
    s1[t] = sd;
    s2[t] = sc;
    __syncthreads();
#pragma unroll
    for (int s = 512; s > 0; s >>= 1) {
        if (t < s) { s1[t] += s1[t + s]; s2[t] += s2[t + s]; }
        __syncthreads();
    }
    if (t == 0) {
        double dist_sum = (double)s1[0] * (1.0 / (double)FXS);
        out[0] = (float)(dist_sum / (double)NP) + 0.1f * s2[0] * (1.0f / (float)(NP * 3));
    }
}

extern "C" void kernel_launch(void* const* d_in, const int* in_sizes, int n_in,
                              void* d_out, int out_size) {
    const float* pred = (const float*)d_in[0];
    const float* gt   = (const float*)d_in[1];
    float* out        = (float*)d_out;
    (void)in_sizes; (void)n_in; (void)out_size;

    bin_kernel<<<(2 * NP) / 256, 256>>>(pred, gt);
    query_kernel<<<(2 * NP * 32) / 256, 256>>>(pred, gt);
    reduce_kernel<<<1, 1024>>>(pred, gt, out);
}

// round 11
// speedup vs baseline: 1.9868x; 1.4452x over previous
#include <cuda_runtime.h>
#include <math_constants.h>

#define NP    16384
#define GRIDD 32
#define NCELL (GRIDD * GRIDD * GRIDD)   // 32768
#define ORG   (-4.5f)
#define WID   (9.0f / GRIDD)            // 0.28125
#define INVW  (GRIDD / 9.0f)
#define FULLM 0xffffffffu
#define FXS   268435456.0f              // 2^28 fixed point
#define CAP   64
#define OVCAP 1024

// ---------------- device scratch (zero-init; finish_kernel re-zeroes
// the mutable counters/accumulators for the next replay) ----------------
__device__ int    g_count[2][NCELL];
__device__ float4 g_bkt[2][NCELL * CAP];
__device__ float4 g_dense[2][NP];
__device__ int    g_ovf_n[2];
__device__ float4 g_ovf[2][OVCAP];
__device__ unsigned long long g_dist_acc;
__device__ unsigned long long g_col_acc;

__device__ __forceinline__ int clampi(int v, int lo, int hi) {
    return v < lo ? lo : (v > hi ? hi : v);
}
__device__ __forceinline__ void cell_of(float x, float y, float z,
                                        int& cx, int& cy, int& cz) {
    cx = clampi((int)floorf((x - ORG) * INVW), 0, GRIDD - 1);
    cy = clampi((int)floorf((y - ORG) * INVW), 0, GRIDD - 1);
    cz = clampi((int)floorf((z - ORG) * INVW), 0, GRIDD - 1);
}
__device__ __forceinline__ float warp_min(float v) {
#pragma unroll
    for (int s = 16; s > 0; s >>= 1)
        v = fminf(v, __shfl_xor_sync(FULLM, v, s));
    return v;
}

// cooperative brute force for ONE query (all 32 lanes participate)
__device__ __forceinline__ float brute_one(const float4* __restrict__ dns,
                                           float qx, float qy, float qz, int lane) {
    float b0 = CUDART_INF_F, b1 = CUDART_INF_F, b2 = CUDART_INF_F, b3 = CUDART_INF_F;
#pragma unroll 8
    for (int p = lane; p < NP; p += 128) {
        float4 ga = dns[p];
        float4 gb = dns[p + 32];
        float4 gc = dns[p + 64];
        float4 gd = dns[p + 96];
        float dx, dy, dz;
        dx = qx - ga.x; dy = qy - ga.y; dz = qz - ga.z;
        b0 = fminf(b0, fmaf(dx, dx, fmaf(dy, dy, dz * dz)));
        dx = qx - gb.x; dy = qy - gb.y; dz = qz - gb.z;
        b1 = fminf(b1, fmaf(dx, dx, fmaf(dy, dy, dz * dz)));
        dx = qx - gc.x; dy = qy - gc.y; dz = qz - gc.z;
        b2 = fminf(b2, fmaf(dx, dx, fmaf(dy, dy, dz * dz)));
        dx = qx - gd.x; dy = qy - gd.y; dz = qz - gd.z;
        b3 = fminf(b3, fmaf(dx, dx, fmaf(dy, dy, dz * dz)));
    }
    return warp_min(fminf(fminf(b0, b1), fminf(b2, b3)));
}

// broadcast one batch of candidates (lane j holds candidate j; valid j < m)
// to every lane's query/queries. Warp-uniform m/dual.
__device__ __forceinline__ void proc_batch(
    float gx, float gy, float gz, int m, bool dual,
    float q1x, float q1y, float q1z,
    float q2x, float q2y, float q2z,
    float& b1, float& b2)
{
    if (!dual) {
        for (int j = 0; j < m; j++) {
            float bx = __shfl_sync(FULLM, gx, j);
            float by = __shfl_sync(FULLM, gy, j);
            float bz = __shfl_sync(FULLM, gz, j);
            float dx = q1x - bx, dy = q1y - by, dz = q1z - bz;
            b1 = fminf(b1, fmaf(dx, dx, fmaf(dy, dy, dz * dz)));
        }
    } else {
        for (int j = 0; j < m; j++) {
            float bx = __shfl_sync(FULLM, gx, j);
            float by = __shfl_sync(FULLM, gy, j);
            float bz = __shfl_sync(FULLM, gz, j);
            float dx = q1x - bx, dy = q1y - by, dz = q1z - bz;
            b1 = fminf(b1, fmaf(dx, dx, fmaf(dy, dy, dz * dz)));
            dx = q2x - bx; dy = q2y - by; dz = q2z - bz;
            b2 = fminf(b2, fmaf(dx, dx, fmaf(dy, dy, dz * dz)));
        }
    }
}

// ---------------- node 1: bin points + dense copy + color loss ----------------
__global__ __launch_bounds__(256)
void bin_kernel(const float* __restrict__ pred, const float* __restrict__ gt) {
    int i = blockIdx.x * blockDim.x + threadIdx.x;   // [0, 2*NP)
    int lane = threadIdx.x & 31;
    int cloud = i >> 14;
    int idx = i & (NP - 1);
    const float* r = (cloud ? gt : pred) + (size_t)idx * 6;
    float x = r[0], y = r[1], z = r[2];
    float4 pt = make_float4(x, y, z, 0.0f);
    g_dense[cloud][idx] = pt;

    int cx, cy, cz;
    cell_of(x, y, z, cx, cy, cz);
    int cell = (cz * GRIDD + cy) * GRIDD + cx;
    int slot = atomicAdd(&g_count[cloud][cell], 1);
    if (slot < CAP) {
        g_bkt[cloud][cell * CAP + slot] = pt;
    } else {
        int o = atomicAdd(&g_ovf_n[cloud], 1);
        if (o < OVCAP) g_ovf[cloud][o] = pt;
    }

    // fused color L1 (cloud-0 threads own point idx; warp-uniform branch)
    long long ci = 0;
    if (cloud == 0) {
        const float* pc = pred + (size_t)idx * 6;
        const float* gc = gt + (size_t)idx * 6;
        float col = fabsf(pc[3] - gc[3]) + fabsf(pc[4] - gc[4]) + fabsf(pc[5] - gc[5]);
        ci = llrintf(col * FXS);        // per-point deterministic
    }
#pragma unroll
    for (int s = 16; s > 0; s >>= 1)
        ci += __shfl_xor_sync(FULLM, ci, s);
    if (lane == 0 && ci != 0)
        atomicAdd(&g_col_acc, (unsigned long long)ci);
}

// ---------------- node 2: exact NN, one WARP per CELL ----------------
// All queries of a cell share its 27-cell candidate neighborhood: the warp
// streams each candidate ONCE and broadcasts it to every lane's query.
__global__ __launch_bounds__(256)
void query_kernel() {
    const int lane = threadIdx.x & 31;

    // ---- overflow-query handler block (normally idle) ----
    if (blockIdx.x == 8192) {
        int w = threadIdx.x >> 5;
        for (int cl = 0; cl < 2; cl++) {
            int n = min(g_ovf_n[cl], OVCAP);
            for (int o = w; o < n; o += 8) {
                float4 q = g_ovf[cl][o];
                float nb = brute_one(g_dense[cl ^ 1], q.x, q.y, q.z, lane);
                if (lane == 0)
                    atomicAdd(&g_dist_acc,
                              (unsigned long long)(long long)llrintf(sqrtf(nb) * FXS));
            }
        }
        return;
    }

    const int wid  = blockIdx.x * 8 + (threadIdx.x >> 5);  // [0, 65536)
    const int cl   = wid >> 15;
    const int cell = wid & (NCELL - 1);
    const int sdb  = cl ^ 1;

    const int nq = min(g_count[cl][cell], CAP);
    if (nq == 0) return;
    const bool dual = (nq > 32);

    const int cx = cell & 31, cy = (cell >> 5) & 31, cz = cell >> 10;

    // load this warp's queries (bucket slots)
    const bool a1 = lane < nq;
    const bool a2 = lane + 32 < nq;
    float4 q1 = make_float4(0.f, 0.f, 0.f, 0.f), q2 = q1;
    if (a1) q1 = g_bkt[cl][cell * CAP + lane];
    if (a2) q2 = g_bkt[cl][cell * CAP + lane + 32];
    // clamped-outside-grid queries invalidate the cell-level bound
    const bool qok1 = !a1 || (q1.x > ORG && q1.x < ORG + 9.0f &&
                              q1.y > ORG && q1.y < ORG + 9.0f &&
                              q1.z > ORG && q1.z < ORG + 9.0f);
    const bool qok2 = !a2 || (q2.x > ORG && q2.x < ORG + 9.0f &&
                              q2.y > ORG && q2.y < ORG + 9.0f &&
                              q2.z > ORG && q2.z < ORG + 9.0f);

    const int*    __restrict__ cnts = g_count[sdb];
    const float4* __restrict__ bkt  = g_bkt[sdb];

    float best1 = CUDART_INF_F, best2 = CUDART_INF_F;

    // opposite-cloud overflow points as candidates (normally none)
    int novf = min(g_ovf_n[sdb], OVCAP);
    for (int i0 = 0; i0 < novf; i0 += 32) {
        int i = i0 + lane;
        float gx = CUDART_INF_F, gy = 0.f, gz = 0.f;
        if (i < novf) { float4 g = g_ovf[sdb][i]; gx = g.x; gy = g.y; gz = g.z; }
        proc_batch(gx, gy, gz, min(32, novf - i0), dual,
                   q1.x, q1.y, q1.z, q2.x, q2.y, q2.z, best1, best2);
    }

    // -------- phase A: flattened 3x3x3, candidates broadcast to all queries ----
    {
        int s = 0, c = 0;
        if (lane < 27) {
            int dz = lane / 9, rem = lane - dz * 9;
            int dy = rem / 3, dx = rem - dy * 3;
            int zc = cz + dz - 1, yc = cy + dy - 1, xc = cx + dx - 1;
            if ((unsigned)zc < GRIDD && (unsigned)yc < GRIDD && (unsigned)xc < GRIDD) {
                int cel = (zc * GRIDD + yc) * GRIDD + xc;
                c = min(cnts[cel], CAP);
                s = cel * CAP;
            }
        }
        int p = c;
#pragma unroll
        for (int d = 1; d < 32; d <<= 1) {
            int v = __shfl_up_sync(FULLM, p, d);
            if (lane >= d) p += v;
        }
        int E  = __shfl_sync(FULLM, p, 26);
        int pe = p - c;
        int S[27], P[27];
#pragma unroll
        for (int r = 0; r < 27; r++) {
            S[r] = __shfl_sync(FULLM, s,  r);
            P[r] = __shfl_sync(FULLM, pe, r);
        }
        for (int i0 = 0; i0 < E; i0 += 32) {
            int i = i0 + lane;
            int addr = S[0] + i;
#pragma unroll
            for (int r = 1; r < 27; r++)
                if (i >= P[r]) addr = S[r] + (i - P[r]);
            float gx = CUDART_INF_F, gy = 0.f, gz = 0.f;
            if (i < E) { float4 g = bkt[addr]; gx = g.x; gy = g.y; gz = g.z; }
            proc_batch(gx, gy, gz, min(32, E - i0), dual,
                       q1.x, q1.y, q1.z, q2.x, q2.y, q2.z, best1, best2);
        }
    }

    // -------- bound checks / escalation --------
    const float B1 = WID * WID;                 // points outside 3^3 box >= WID from cell
    unsigned bad = __ballot_sync(FULLM,
        (a1 && (!qok1 || best1 > B1)) || (a2 && (!qok2 || best2 > B1)));

    if (bad) {
        // -------- phase B: flattened 5x5x5 (rescans inner; rare warps) ----
        for (int cb = 0; cb < 125; cb += 32) {
            int cc2 = cb + lane;
            int s2 = 0, c2 = 0;
            if (cc2 < 125) {
                int dz = cc2 / 25, rem = cc2 - dz * 25;
                int dy = rem / 5, dxx = rem - dy * 5;
                int zc = cz + dz - 2, yc = cy + dy - 2, xc = cx + dxx - 2;
                if ((unsigned)zc < GRIDD && (unsigned)yc < GRIDD && (unsigned)xc < GRIDD) {
                    int cel = (zc * GRIDD + yc) * GRIDD + xc;
                    c2 = min(cnts[cel], CAP);
                    s2 = cel * CAP;
                }
            }
            int p2 = c2;
#pragma unroll
            for (int d = 1; d < 32; d <<= 1) {
                int v = __shfl_up_sync(FULLM, p2, d);
                if (lane >= d) p2 += v;
            }
            int E2  = __shfl_sync(FULLM, p2, 31);
            int pe2 = p2 - c2;
            int SS[32], PP[32];
#pragma unroll
            for (int r = 0; r < 32; r++) {
                SS[r] = __shfl_sync(FULLM, s2,  r);
                PP[r] = __shfl_sync(FULLM, pe2, r);
            }
            for (int i0 = 0; i0 < E2; i0 += 32) {
                int i = i0 + lane;
                int addr = SS[0] + i;
#pragma unroll
                for (int r = 1; r < 32; r++)
                    if (i >= PP[r]) addr = SS[r] + (i - PP[r]);
                float gx = CUDART_INF_F, gy = 0.f, gz = 0.f;
                if (i < E2) { float4 g = bkt[addr]; gx = g.x; gy = g.y; gz = g.z; }
                proc_batch(gx, gy, gz, min(32, E2 - i0), dual,
                           q1.x, q1.y, q1.z, q2.x, q2.y, q2.z, best1, best2);
            }
        }

        // -------- phase C: per-query cooperative brute (rarer) ----
        const float B2 = 4.0f * WID * WID;      // outside 5^3 box >= 2*WID
        const float4* __restrict__ dns = g_dense[sdb];
        unsigned f1 = __ballot_sync(FULLM, a1 && (!qok1 || best1 > B2));
        while (f1) {
            int r = __ffs(f1) - 1;
            f1 &= f1 - 1;
            float fx = __shfl_sync(FULLM, q1.x, r);
            float fy = __shfl_sync(FULLM, q1.y, r);
            float fz = __shfl_sync(FULLM, q1.z, r);
            float nb = brute_one(dns, fx, fy, fz, lane);
            if (lane == r) best1 = nb;
        }
        unsigned f2 = __ballot_sync(FULLM, a2 && (!qok2 || best2 > B2));
        while (f2) {
            int r = __ffs(f2) - 1;
            f2 &= f2 - 1;
            float fx = __shfl_sync(FULLM, q2.x, r);
            float fy = __shfl_sync(FULLM, q2.y, r);
            float fz = __shfl_sync(FULLM, q2.z, r);
            float nb = brute_one(dns, fx, fy, fz, lane);
            if (lane == r) best2 = nb;
        }
    }

    // -------- accumulate (int64 fixed point: order-invariant) --------
    long long di = 0;
    if (a1) di += (long long)llrintf(sqrtf(best1) * FXS);
    if (a2) di += (long long)llrintf(sqrtf(best2) * FXS);
#pragma unroll
    for (int s = 16; s > 0; s >>= 1)
        di += __shfl_xor_sync(FULLM, di, s);
    if (lane == 0 && di != 0)
        atomicAdd(&g_dist_acc, (unsigned long long)di);
}

// ---------------- node 3: combine + reset for next replay ----------------
__global__ __launch_bounds__(1024)
void finish_kernel(float* __restrict__ out) {
    const int t = threadIdx.x;
    if (t == 0) {
        double dist = (double)(long long)g_dist_acc * (1.0 / 268435456.0);
        double col  = (double)(long long)g_col_acc  * (1.0 / 268435456.0);
        out[0] = (float)(dist / (double)NP + 0.1 * col / (double)(NP * 3));
        g_dist_acc = 0;
        g_col_acc  = 0;
        g_ovf_n[0] = 0;
        g_ovf_n[1] = 0;
    }
    int* cc = (int*)g_count;
#pragma unroll
    for (int j = 0; j < 64; j++)
        cc[t + j * 1024] = 0;
}

extern "C" void kernel_launch(void* const* d_in, const int* in_sizes, int n_in,
                              void* d_out, int out_size) {
    const float* pred = (const float*)d_in[0];
    const float* gt   = (const float*)d_in[1];
    float* out        = (float*)d_out;
    (void)in_sizes; (void)n_in; (void)out_size;

    bin_kernel<<<(2 * NP) / 256, 256>>>(pred, gt);
    query_kernel<<<8193, 256>>>();
    finish_kernel<<<1, 1024>>>(out);
}